// round 1
// baseline (speedup 1.0000x reference)
#include <cuda_runtime.h>
#include <stdint.h>

// samx_qkv_1bit: suffix-automaton retrieval, 1024 independent serial rows.
// Strategy: one warp per row (lane 0 active, zero divergence), SAM tables in
// shared memory (tr + f/m packed u32, 16-bit fields), r[] in global scratch.
// 7 rows/block * 32KB = 224KB smem -> 147 blocks = one wave on 148 SMs.

#define BB 4
#define TT 2048
#define CC 256
#define NROWS (BB*CC)          // 1024
#define WPB (TT/32)            // 64 packed words per row
#define STATES 4096            // SAM has <= 2n-1 = 4095 states
#define RPB 7                  // rows (warps) per block

__device__ uint32_t g_qpack[NROWS*WPB];
__device__ uint32_t g_kpack[NROWS*WPB];
__device__ uint32_t g_vpack[NROWS*WPB];
__device__ int16_t  g_r[(size_t)NROWS*STATES];

// ---------------------------------------------------------------------------
// Pack kernel: binarize q,k,v into per-row bitstreams. Coalesced over c.
// grid = (WPB, BB), block = CC threads.
// ---------------------------------------------------------------------------
__global__ void samx_pack_kernel(const float* __restrict__ q,
                                 const float* __restrict__ k,
                                 const float* __restrict__ v) {
    int c  = threadIdx.x;
    int wi = blockIdx.x;
    int b  = blockIdx.y;
    int row = b * CC + c;
    size_t base = ((size_t)b * TT + (size_t)wi * 32) * CC + c;
    uint32_t qw = 0, kw = 0, vw = 0;
#pragma unroll
    for (int s = 0; s < 32; s++) {
        if (q[base + (size_t)s * CC] > 0.f) qw |= 1u << s;
        if (k[base + (size_t)s * CC] > 0.f) kw |= 1u << s;
        if (v[base + (size_t)s * CC] > 0.f) vw |= 1u << s;
    }
    g_qpack[row * WPB + wi] = qw;
    g_kpack[row * WPB + wi] = kw;
    g_vpack[row * WPB + wi] = vw;
}

// ---------------------------------------------------------------------------
// Main SAM kernel. Per row:
//   tr[s] : u32 = (trans1 << 16) | trans0, 0xFFFF = absent
//   fm[s] : u32 = (maxlen << 16) | flink,  0xFFFF = flink -1
//   rr[s] : int16 last end position (global scratch)
// Proven simplifications vs reference:
//   - r-propagation guard r[vst] < i is always true -> pure f-walk + stores
//   - query back-off loop only fires at root -> y = (x>0) ? vbit(r[vst]+1) : 0
//   - m[last] == i -> no load for m[j] = m[g]+1
// ---------------------------------------------------------------------------
extern "C" __global__ void __launch_bounds__(32*RPB, 1)
samx_sam_kernel(const float* __restrict__ e, float* __restrict__ out) {
    extern __shared__ uint32_t smem[];
    int warp = threadIdx.x >> 5;
    int lane = threadIdx.x & 31;
    int row  = blockIdx.x * RPB + warp;
    if (lane != 0 || row >= NROWS) return;

    uint32_t* tr = smem + warp * (2 * STATES);
    uint32_t* fm = tr + STATES;
    int16_t*  rr = g_r + (size_t)row * STATES;
    const uint32_t* qpk = g_qpack + row * WPB;
    const uint32_t* kpk = g_kpack + row * WPB;
    const uint32_t* vpk = g_vpack + row * WPB;

    int b = row >> 8;
    int c = row & (CC - 1);
    float ev = e[c];
    float* op = out + (size_t)b * TT * CC + c;

    // root state
    tr[0] = 0xFFFFFFFFu;           // no transitions
    fm[0] = 0x0000FFFFu;           // m=0, f=-1

    int g = 0, u = 1, w = 0, h = 0;
    uint32_t qw = 0, kw = 0;

    for (int i = 0; i < TT; i++) {
        if ((i & 31) == 0) { int wi = i >> 5; qw = qpk[wi]; kw = kpk[wi]; }
        int qshift = ((qw >> (i & 31)) & 1) << 4;   // 0 or 16
        int kshift = ((kw >> (i & 31)) & 1) << 4;

        // ---- query: extend match with symbol q via suffix links ----
        int p = w, x = h;
        for (;;) {
            if (p < 0) { p = 0; x = 0; break; }
            uint32_t t = tr[p];
            int tq = (int)((t >> qshift) & 0xFFFFu);
            if (tq != 0xFFFF) { p = tq; x += 1; break; }
            uint32_t fv = fm[p];
            int mp = (int)(fv >> 16);
            if (x > mp) x = mp;
            int f = (int)(fv & 0xFFFFu);
            p = (f == 0xFFFF) ? -1 : f;
        }
        int y = 0;
        if (x > 0) {
            // tightest state with m >= x
            int vst = p;
            for (;;) {
                int f = (int)(fm[vst] & 0xFFFFu);
                if (f == 0xFFFF) break;
                if ((int)(fm[f] >> 16) >= x) vst = f; else break;
            }
            int idx = (int)rr[vst] + 1;
            y = (int)((vpk[idx >> 5] >> (idx & 31)) & 1u);
        }
        op[(size_t)i * CC] = (float)(2 * y - 1) * ev;
        w = p; h = x;

        // ---- key: standard SAM extension with symbol k ----
        int j = u++;
        tr[j] = 0xFFFFFFFFu;
        int p2 = g;
        int fj;
        for (;;) {
            if (p2 < 0) { fj = 0; break; }
            uint32_t t = tr[p2];
            int tk = (int)((t >> kshift) & 0xFFFFu);
            if (tk == 0xFFFF) {
                tr[p2] = (t & ~(0xFFFFu << kshift)) | ((uint32_t)j << kshift);
                int f = (int)(fm[p2] & 0xFFFFu);
                p2 = (f == 0xFFFF) ? -1 : f;
            } else {
                int d = tk;
                uint32_t fmd = fm[d];
                int md = (int)(fmd >> 16);
                int mp = (int)(fm[p2] >> 16);
                if (mp + 1 == md) {
                    fj = d;
                } else {
                    int bc = u++;                      // clone
                    tr[bc] = tr[d];
                    fm[bc] = (fmd & 0xFFFFu) | ((uint32_t)(mp + 1) << 16);
                    rr[bc] = rr[d];
                    fm[d]  = (fmd & 0xFFFF0000u) | (uint32_t)bc;
                    fj = bc;
                    for (;;) {                         // redirect tk==d -> bc
                        uint32_t t2 = tr[p2];
                        if (((t2 >> kshift) & 0xFFFFu) != (uint32_t)d) break;
                        tr[p2] = (t2 & ~(0xFFFFu << kshift)) | ((uint32_t)bc << kshift);
                        int f = (int)(fm[p2] & 0xFFFFu);
                        if (f == 0xFFFF) break;
                        p2 = f;
                    }
                }
                break;
            }
        }
        fm[j] = (uint32_t)fj | ((uint32_t)(i + 1) << 16);   // m[j] = m[g]+1 = i+1
        g = j;

        // ---- propagate last end position up the suffix chain ----
        int vst = j;
        for (;;) {
            rr[vst] = (int16_t)i;
            int f = (int)(fm[vst] & 0xFFFFu);
            if (f == 0xFFFF) break;
            vst = f;
        }
    }
}

extern "C" void kernel_launch(void* const* d_in, const int* in_sizes, int n_in,
                              void* d_out, int out_size) {
    const float* q = (const float*)d_in[0];
    const float* k = (const float*)d_in[1];
    const float* v = (const float*)d_in[2];
    const float* e = (const float*)d_in[3];
    float* out = (float*)d_out;

    dim3 pg(WPB, BB);
    samx_pack_kernel<<<pg, CC>>>(q, k, v);

    size_t smem = (size_t)RPB * 2 * STATES * sizeof(uint32_t);  // 229376 B
    cudaFuncSetAttribute(samx_sam_kernel,
                         cudaFuncAttributeMaxDynamicSharedMemorySize, (int)smem);
    int blocks = (NROWS + RPB - 1) / RPB;                       // 147
    samx_sam_kernel<<<blocks, 32 * RPB, smem>>>(e, out);
}

// round 2
// speedup vs baseline: 1.3764x; 1.3764x over previous
#include <cuda_runtime.h>
#include <stdint.h>

// samx_qkv_1bit: suffix-automaton retrieval, 1024 independent serial rows.
// R2: single 64-bit state record {tr0:13, tr1:13, f:13, m:12, r+1:12} in smem
//     -> one LDS.64 per walk node (was 2-3 LDS + global rr load).
//     vpk also in smem -> zero global loads on the per-step critical path.
// 7 rows/block * (32KB records + 256B vpk) = 231168 B smem, 147 blocks = 1 wave.

#define BB 4
#define TT 2048
#define CC 256
#define NROWS (BB*CC)          // 1024
#define WPB (TT/32)            // 64 packed words per row
#define STATES 4096            // SAM has <= 2n-1 = 4095 states
#define RPB 7                  // rows (warps) per block

#define F_SHIFT 26
#define M_SHIFT 39
#define R_SHIFT 51
#define ID_MASK 0x1FFFull      // 13-bit state id / transition, 0x1FFF = absent/-1
#define M_MASK  0xFFFull
#define ABSENT  0x1FFF

__device__ uint32_t g_qpack[NROWS*WPB];
__device__ uint32_t g_kpack[NROWS*WPB];
__device__ uint32_t g_vpack[NROWS*WPB];

// ---------------------------------------------------------------------------
// Pack kernel: binarize q,k,v into per-row bitstreams. Coalesced over c.
// ---------------------------------------------------------------------------
__global__ void samx_pack_kernel(const float* __restrict__ q,
                                 const float* __restrict__ k,
                                 const float* __restrict__ v) {
    int c  = threadIdx.x;
    int wi = blockIdx.x;
    int b  = blockIdx.y;
    int row = b * CC + c;
    size_t base = ((size_t)b * TT + (size_t)wi * 32) * CC + c;
    uint32_t qw = 0, kw = 0, vw = 0;
#pragma unroll
    for (int s = 0; s < 32; s++) {
        if (q[base + (size_t)s * CC] > 0.f) qw |= 1u << s;
        if (k[base + (size_t)s * CC] > 0.f) kw |= 1u << s;
        if (v[base + (size_t)s * CC] > 0.f) vw |= 1u << s;
    }
    g_qpack[row * WPB + wi] = qw;
    g_kpack[row * WPB + wi] = kw;
    g_vpack[row * WPB + wi] = vw;
}

// ---------------------------------------------------------------------------
// Main SAM kernel: one warp per row, lane 0 active. All state in smem.
// ---------------------------------------------------------------------------
extern "C" __global__ void __launch_bounds__(32*RPB, 1)
samx_sam_kernel(const float* __restrict__ e, float* __restrict__ out) {
    extern __shared__ unsigned long long smem[];
    int warp = threadIdx.x >> 5;
    int lane = threadIdx.x & 31;
    int row  = blockIdx.x * RPB + warp;

    unsigned long long* S = smem + (size_t)warp * STATES;
    uint32_t* vpk_s = (uint32_t*)(smem + (size_t)RPB * STATES) + warp * WPB;

    // cooperative vpk copy (global -> smem), 64 words per row, 2 per lane
    if (row < NROWS) {
        vpk_s[lane]      = g_vpack[row * WPB + lane];
        vpk_s[lane + 32] = g_vpack[row * WPB + lane + 32];
    }
    __syncwarp();
    if (lane != 0 || row >= NROWS) return;

    const uint32_t* qpk = g_qpack + row * WPB;
    const uint32_t* kpk = g_kpack + row * WPB;

    int b = row >> 8;
    int c = row & (CC - 1);
    float ev = e[c];
    float* op = out + (size_t)b * TT * CC + c;

    // root: tr absent, f=-1, m=0, r+1=0
    S[0] = ID_MASK | (ID_MASK << 13) | (ID_MASK << F_SHIFT);

    int g = 0, u = 1, w = 0, h = 0;
    uint32_t qw = 0, kw = 0;

    for (int i = 0; i < TT; i++) {
        if ((i & 31) == 0) { int wi = i >> 5; qw = qpk[wi]; kw = kpk[wi]; }
        int qs = ((qw >> (i & 31)) & 1) ? 13 : 0;
        int ks = ((kw >> (i & 31)) & 1) ? 13 : 0;

        // ---- query: extend match with symbol q via suffix links ----
        int p = w, x = h;
        for (;;) {
            if (p < 0) { p = 0; x = 0; break; }
            unsigned long long rec = S[p];
            int tq = (int)((rec >> qs) & ID_MASK);
            if (tq != ABSENT) { p = tq; x += 1; break; }
            int mp = (int)((rec >> M_SHIFT) & M_MASK);
            if (x > mp) x = mp;
            int f = (int)((rec >> F_SHIFT) & ID_MASK);
            p = (f == ABSENT) ? -1 : f;
        }
        int y = 0;
        if (x > 0) {
            // tightest state with m >= x; its record already holds r
            unsigned long long recv = S[p];
            for (;;) {
                int f = (int)((recv >> F_SHIFT) & ID_MASK);
                if (f == ABSENT) break;
                unsigned long long recf = S[f];
                if ((int)((recf >> M_SHIFT) & M_MASK) >= x) recv = recf;
                else break;
            }
            int idx = (int)(recv >> R_SHIFT);           // r+1 (bits 51..62)
            y = (int)((vpk_s[idx >> 5] >> (idx & 31)) & 1u);
        }
        op[(size_t)i * CC] = y ? ev : -ev;
        w = p; h = x;

        // ---- key: standard SAM extension with symbol k ----
        int j = u++;
        int p2 = g;
        int fj;
        for (;;) {
            if (p2 < 0) { fj = 0; break; }
            unsigned long long t = S[p2];
            int tk = (int)((t >> ks) & ID_MASK);
            if (tk == ABSENT) {
                S[p2] = (t & ~(ID_MASK << ks)) | ((unsigned long long)j << ks);
                int f = (int)((t >> F_SHIFT) & ID_MASK);
                p2 = (f == ABSENT) ? -1 : f;
            } else {
                int d = tk;
                unsigned long long recd = S[d];
                int md = (int)((recd >> M_SHIFT) & M_MASK);
                int mp = (int)((t >> M_SHIFT) & M_MASK);
                if (mp + 1 == md) {
                    fj = d;
                } else {
                    int bc = u++;                      // clone of d with m = mp+1
                    S[bc] = (recd & ~(M_MASK << M_SHIFT))
                          | ((unsigned long long)(mp + 1) << M_SHIFT);
                    S[d]  = (recd & ~(ID_MASK << F_SHIFT))
                          | ((unsigned long long)bc << F_SHIFT);
                    fj = bc;
                    for (;;) {                         // redirect tk==d -> bc
                        unsigned long long t2 = S[p2];
                        if (((t2 >> ks) & ID_MASK) != (unsigned long long)d) break;
                        S[p2] = (t2 & ~(ID_MASK << ks))
                              | ((unsigned long long)bc << ks);
                        int f = (int)((t2 >> F_SHIFT) & ID_MASK);
                        if (f == ABSENT) break;
                        p2 = f;
                    }
                }
                break;
            }
        }
        // new state j: tr absent, f=fj, m=i+1, r+1=0 (set by propagation below)
        S[j] = ID_MASK | (ID_MASK << 13)
             | ((unsigned long long)fj << F_SHIFT)
             | ((unsigned long long)(i + 1) << M_SHIFT);
        g = j;

        // ---- propagate last end position up the suffix chain ----
        unsigned long long rset = ((unsigned long long)(i + 1)) << R_SHIFT; // r+1 = i+1
        int vst = j;
        for (;;) {
            unsigned long long rec = S[vst];
            S[vst] = (rec & ~(M_MASK << R_SHIFT)) | rset;
            int f = (int)((rec >> F_SHIFT) & ID_MASK);
            if (f == ABSENT) break;
            vst = f;
        }
    }
}

extern "C" void kernel_launch(void* const* d_in, const int* in_sizes, int n_in,
                              void* d_out, int out_size) {
    const float* q = (const float*)d_in[0];
    const float* k = (const float*)d_in[1];
    const float* v = (const float*)d_in[2];
    const float* e = (const float*)d_in[3];
    float* out = (float*)d_out;

    dim3 pg(WPB, BB);
    samx_pack_kernel<<<pg, CC>>>(q, k, v);

    size_t smem = (size_t)RPB * STATES * sizeof(unsigned long long)
                + (size_t)RPB * WPB * sizeof(uint32_t);   // 229376 + 1792 = 231168
    cudaFuncSetAttribute(samx_sam_kernel,
                         cudaFuncAttributeMaxDynamicSharedMemorySize, (int)smem);
    int blocks = (NROWS + RPB - 1) / RPB;                 // 147
    samx_sam_kernel<<<blocks, 32 * RPB, smem>>>(e, out);
}